// round 15
// baseline (speedup 1.0000x reference)
#include <cuda_runtime.h>

#define NCONF   8
#define NATOMS  10
#define NSTATES 4
#define NBASIS  24
#define HIDDEN  48
#define NTYPES  4
#define PPC     90            // ordered pairs, contiguous: p = i*9 + (j - (j>i))
#define NT      1024
#define NBLOCKS (NCONF*NATOMS)
#define NARRIVE (NBLOCKS*3)   // 3 mu-warps per block arrive at the counter

#define PI_F 3.14159265358979323846f
#define CUT  6.0f
#define KARG (PI_F/CUT)
#define AL   1.5f
#define DLT  (CUT/23.0f)
#define FULLM 0xffffffffu

// cross-block scratch (no cudaMalloc allowed)
__device__ __align__(16) float g_kinCS[NCONF*NSTATES];
__device__ float g_T[NCONF*NSTATES];
__device__ int   g_fin;

__device__ __forceinline__ int jlA(int t, int A) { return t + (t >= A); }

__device__ __forceinline__ float fast_tanh(float u) {
    float ex = __expf(2.f*u);
    return 1.f - __fdividef(2.f, ex + 1.f);
}

__global__ void __launch_bounds__(NT, 1)
fused_kernel(const float* __restrict__ pot, const float* __restrict__ cart,
             const int* __restrict__ species, const float* __restrict__ massrev,
             const float* __restrict__ W1, const float* __restrict__ B1,
             const float* __restrict__ W2, const float* __restrict__ Emb,
             const float* __restrict__ elevel, float* __restrict__ out)
{
    __shared__ __align__(16) float W1s[NBASIS][52];
    __shared__ __align__(16) float W2s[HIDDEN][4];
    __shared__ float B1all[NTYPES][48];
    __shared__ float EmbAll[NTYPES][4];
    __shared__ int   s_sp[NATOMS];
    __shared__ float s_mass, s_el[4];
    __shared__ float G0[PPC][25];
    __shared__ float radv[PPC];
    __shared__ float G1k[18][25], G2k[18][25];
    __shared__ float rad1k[18], rad2k[18];
    __shared__ float wdd[3][18], wdh[3][18];
    __shared__ float Rr[NATOMS];
    __shared__ float tval[NATOMS][49], f1a[NATOMS][49], f2a[NATOMS][49];
    __shared__ __align__(16) float U1[18][52], U2[18][52];
    __shared__ float pv[NATOMS][4];
    __shared__ float V1[18][4], V2[18][4], Qn[9][4];
    __shared__ float QA[3][4];
    __shared__ float wpd[3][NATOMS][4], wph[3][NATOMS][4];

    const int tid  = threadIdx.x;
    const int w    = tid >> 5;
    const int lane = tid & 31;
    const int c    = blockIdx.x / NATOMS;
    const int A    = blockIdx.x % NATOMS;
    const float* cb = cart + c*NATOMS*3;

    // prefetch pot for the finalize path (warps 0-2; any of them may finalize)
    float potA = 0.f, potLast = 0.f;
    if (w < 3) { potA = pot[lane >> 2]; potLast = pot[NCONF-1]; }

    // -------- Phase A: weight loads + pair geometry, one phase --------
    if (tid < PPC) {
        const int p = tid;
        const int i = p / 9, jr = p % 9;
        const int j = jr + (jr >= i);
        float dx = cb[j*3+0] - cb[i*3+0];
        float dy = cb[j*3+1] - cb[i*3+1];
        float dz = cb[j*3+2] - cb[i*3+2];
        float d2 = fmaf(dx, dx, fmaf(dy, dy, dz*dz));
        float d  = sqrtf(d2);
        float arg = d * KARG;
        float sn = __sinf(arg), cs = __cosf(arg);
        radv[p] = sn*sn*sn;
        float f0 = (d < CUT) ? 0.5f*(cs + 1.f) : 0.f;

        const float gg = __expf(-2.f*AL*DLT*DLT);
        float gg2 = gg*gg, gg3 = gg2*gg, gg6 = gg3*gg3;
        float tc = __expf(fmaf(2.f*AL*DLT, d, -AL*DLT*DLT));
        float t0 = tc, t1 = tc*gg6, t2 = t1*gg6, t3 = t2*gg6;
        float rb0  = __expf(-AL*d2);
        float d6   = d -  6.f*DLT; float rb6  = __expf(-AL*d6*d6);
        float d12  = d - 12.f*DLT; float rb12 = __expf(-AL*d12*d12);
        float d18  = d - 18.f*DLT; float rb18 = __expf(-AL*d18*d18);
        #pragma unroll
        for (int i2 = 0; i2 < 6; i2++) {
            G0[p][i2]      = rb0 *f0;
            G0[p][6 + i2]  = rb6 *f0;
            G0[p][12 + i2] = rb12*f0;
            G0[p][18 + i2] = rb18*f0;
            rb0 *= t0; rb6 *= t1; rb12 *= t2; rb18 *= t3;
            t0 *= gg; t1 *= gg; t2 *= gg; t3 *= gg;
        }
    } else if (tid >= 96 && tid < 96 + 36) {
        // A-pair jets: (k, bhalf) split, 36 threads, direct cart loads
        const int idx = tid - 96;
        const int k     = idx >> 1;
        const int bhalf = idx & 1;
        const int b0    = bhalf * 12;
        const bool isC = (k < 9);
        const int i = isC ? A : jlA(k - 9, A);
        const int j = isC ? jlA(k, A) : A;
        float dx = cb[j*3+0] - cb[i*3+0];
        float dy = cb[j*3+1] - cb[i*3+1];
        float dz = cb[j*3+2] - cb[i*3+2];
        float d2 = fmaf(dx, dx, fmaf(dy, dy, dz*dz));
        float d  = sqrtf(d2);
        float arg = d * KARG;
        float sn = __sinf(arg), cs = __cosf(arg);
        float f0, fd1, fd2;
        if (d < CUT) {
            f0  = 0.5f*(cs + 1.f);
            fd1 = -0.5f*KARG*sn;
            fd2 = -0.5f*KARG*KARG*cs;
        } else { f0 = 0.f; fd1 = 0.f; fd2 = 0.f; }
        if (bhalf == 0) {
            rad1k[k] = 3.f*sn*sn*cs * KARG;
            rad2k[k] = (6.f*sn*cs*cs - 3.f*sn*sn*sn) * (KARG*KARG);
            float invd = __frcp_rn(d);
            float sgn = isC ? -1.f : 1.f;
            float ex = dx*invd, ey = dy*invd, ez = dz*invd;
            wdd[0][k] = sgn*ex; wdh[0][k] = (1.f - ex*ex)*invd;
            wdd[1][k] = sgn*ey; wdh[1][k] = (1.f - ey*ey)*invd;
            wdd[2][k] = sgn*ez; wdh[2][k] = (1.f - ez*ez)*invd;
        }
        const float gg = __expf(-2.f*AL*DLT*DLT);
        float gg2 = gg*gg, gg3 = gg2*gg, gg6 = gg3*gg3;
        float tc  = __expf(fmaf(2.f*AL*DLT, d, -AL*DLT*DLT));
        float ggb = bhalf ? gg6*gg6 : 1.f;
        float ta = tc * ggb;
        float tb = ta * gg6;
        float da  = d - (float)b0*DLT;      float rba = __expf(-AL*da*da);
        float db_ = d - (float)(b0+6)*DLT;  float rbb = __expf(-AL*db_*db_);
        #pragma unroll
        for (int i2 = 0; i2 < 6; i2++) {
            int ba = b0 + i2, bb = b0 + 6 + i2;
            float t_a = d - (float)ba*DLT;
            float r1a = -2.f*AL*t_a*rba;
            float r2a = (4.f*AL*AL*t_a*t_a - 2.f*AL)*rba;
            G1k[k][ba] = r1a*f0 + rba*fd1;
            G2k[k][ba] = r2a*f0 + 2.f*r1a*fd1 + rba*fd2;
            float t_b = d - (float)bb*DLT;
            float r1b = -2.f*AL*t_b*rbb;
            float r2b = (4.f*AL*AL*t_b*t_b - 2.f*AL)*rbb;
            G1k[k][bb] = r1b*f0 + rbb*fd1;
            G2k[k][bb] = r2b*f0 + 2.f*r1b*fd1 + rbb*fd2;
            rba *= ta; rbb *= tb; ta *= gg; tb *= gg;
        }
    } else if (tid >= 160 && tid < 160 + 384) {
        // W1 (1152 floats) on 384 threads (3 each)
        const int base = tid - 160;
        #pragma unroll
        for (int r = 0; r < 3; r++) {
            int i = base + r*384;
            W1s[i / HIDDEN][i % HIDDEN] = W1[i];
        }
    } else if (tid >= 544 && tid < 544 + 48) {
        const int base = tid - 544;
        #pragma unroll
        for (int r = 0; r < 4; r++) {
            int i = base + r*48;
            W2s[i >> 2][i & 3] = W2[i];
        }
    } else if (tid >= 592 && tid < 592 + 48) {
        const int base = tid - 592;
        #pragma unroll
        for (int r = 0; r < 4; r++) {
            int i = base + r*48;
            B1all[i / 48][i % 48] = B1[i];
        }
    } else if (tid >= 640 && tid < 640 + 16) {
        int i = tid - 640;
        EmbAll[i >> 2][i & 3] = Emb[i];
    } else if (tid >= 656 && tid < 656 + NATOMS) {
        s_sp[tid - 656] = species[c*NATOMS + (tid - 656)];
    } else if (tid == 666) {
        s_mass = massrev[c*NATOMS + A];
    } else if (tid >= 668 && tid < 668 + NSTATES) {
        s_el[tid - 668] = elevel[tid - 668];
    }
    __syncthreads();

    // -------- Phase B: U1/U2 + tanh (inline shfl-densv) + Rr, one phase --------
    if (tid < 448) {
        const int idx = tid;
        const bool valid = idx < 432;
        int k  = idx / 24; if (k > 17) k = 17;
        const int rem = idx % 24;
        const int hq = (rem >> 1) * 4;
        const int bhalf = rem & 1;
        const int b0 = bhalf * 12;
        float a0=0,a1=0,a2=0,a3=0, c0=0,c1=0,c2=0,c3=0;
        #pragma unroll
        for (int bi = 0; bi < 12; bi++) {
            int b = b0 + bi;
            float g1 = G1k[k][b], g2 = G2k[k][b];
            float4 wv = *(const float4*)&W1s[b][hq];
            a0 = fmaf(g1, wv.x, a0); a1 = fmaf(g1, wv.y, a1);
            a2 = fmaf(g1, wv.z, a2); a3 = fmaf(g1, wv.w, a3);
            c0 = fmaf(g2, wv.x, c0); c1 = fmaf(g2, wv.y, c1);
            c2 = fmaf(g2, wv.z, c2); c3 = fmaf(g2, wv.w, c3);
        }
        a0 += __shfl_xor_sync(FULLM, a0, 1);
        a1 += __shfl_xor_sync(FULLM, a1, 1);
        a2 += __shfl_xor_sync(FULLM, a2, 1);
        a3 += __shfl_xor_sync(FULLM, a3, 1);
        c0 += __shfl_xor_sync(FULLM, c0, 1);
        c1 += __shfl_xor_sync(FULLM, c1, 1);
        c2 += __shfl_xor_sync(FULLM, c2, 1);
        c3 += __shfl_xor_sync(FULLM, c3, 1);
        if (valid && bhalf == 0) {
            U1[k][hq]=a0; U1[k][hq+1]=a1; U1[k][hq+2]=a2; U1[k][hq+3]=a3;
            U2[k][hq]=c0; U2[k][hq+1]=c1; U2[k][hq+2]=c2; U2[k][hq+3]=c3;
        }
    } else if (w >= 14 && w < 14 + NATOMS) {
        // tanh path: warp = atom; lanes 0-23 own densv elements, shfl-broadcast
        const int at = w - 14;
        float dens = 0.f;
        if (lane < NBASIS) {
            float e0 = 0.f, e1 = 0.f;
            #pragma unroll
            for (int r = 0; r < 8; r += 2) {
                e0 += G0[at*9 + r][lane];
                e1 += G0[at*9 + r + 1][lane];
            }
            dens = e0 + e1 + G0[at*9 + 8][lane];
        }
        const int sp  = s_sp[at];
        const int hh1 = lane;               // 0..31
        const int hh2 = 32 + (lane & 15);   // lanes 0..15 write
        float uA0 = B1all[sp][hh1], uA1 = 0.f;
        float uB0 = B1all[sp][hh2], uB1 = 0.f;
        #pragma unroll
        for (int b = 0; b < NBASIS; b += 2) {
            float d0 = __shfl_sync(FULLM, dens, b);
            float d1 = __shfl_sync(FULLM, dens, b+1);
            uA0 = fmaf(d0, W1s[b  ][hh1], uA0);
            uA1 = fmaf(d1, W1s[b+1][hh1], uA1);
            uB0 = fmaf(d0, W1s[b  ][hh2], uB0);
            uB1 = fmaf(d1, W1s[b+1][hh2], uB1);
        }
        {
            float t1 = fast_tanh(uA0 + uA1);
            float f1 = 1.f - t1*t1;
            tval[at][hh1] = t1;
            f1a[at][hh1]  = f1;
            f2a[at][hh1]  = -2.f*t1*f1;
        }
        if (lane < 16) {
            float t2 = fast_tanh(uB0 + uB1);
            float f1 = 1.f - t2*t2;
            tval[at][hh2] = t2;
            f1a[at][hh2]  = f1;
            f2a[at][hh2]  = -2.f*t2*f1;
        }
    } else if (w == 24) {
        if (lane < NATOMS) {
            float r = 0.f;
            #pragma unroll
            for (int j = 0; j < NATOMS; j++)
                if (j != lane) r += radv[j*9 + (lane - (lane > j))];
            Rr[lane] = r;
        }
    }
    __syncthreads();

    // -------- Phase C: pv (w0-2), V1/V2 (w4-8), Qn (w9), QA (w10-12) --------
    if (w < 3) {
        const bool valid = tid < 80;
        int at = tid >> 3; if (at > 9) at = 9;
        const int s = (tid >> 1) & 3;
        const int half = tid & 1;
        const int h0 = half * 24;
        float a0 = 0.f, a1 = 0.f;
        #pragma unroll
        for (int hi = 0; hi < 24; hi += 2) {
            a0 = fmaf(tval[at][h0+hi  ], W2s[h0+hi  ][s], a0);
            a1 = fmaf(tval[at][h0+hi+1], W2s[h0+hi+1][s], a1);
        }
        float v = a0 + a1;
        v += __shfl_xor_sync(FULLM, v, 1);
        if (valid && half == 0) pv[at][s] = v + EmbAll[s_sp[at]][s];
    } else if (w >= 4 && w <= 8) {
        const int idx = tid - 128;
        const bool valid = idx < 144;
        int k = idx >> 3; if (k > 17) k = 17;
        const int which = (idx >> 2) & 1;
        const int quarter = idx & 3;
        const int cen = (k < 9) ? A : jlA(k - 9, A);
        const int h0 = quarter * 12;
        float v0=0,v1=0,v2=0,v3=0;
        #pragma unroll
        for (int hi = 0; hi < 12; hi++) {
            int hh = h0 + hi;
            float u = (which ? U2[k][hh] : U1[k][hh]) * f1a[cen][hh];
            float4 wv = *(const float4*)&W2s[hh][0];
            v0 = fmaf(u, wv.x, v0); v1 = fmaf(u, wv.y, v1);
            v2 = fmaf(u, wv.z, v2); v3 = fmaf(u, wv.w, v3);
        }
        #pragma unroll
        for (int off = 1; off <= 2; off <<= 1) {
            v0 += __shfl_xor_sync(FULLM, v0, off);
            v1 += __shfl_xor_sync(FULLM, v1, off);
            v2 += __shfl_xor_sync(FULLM, v2, off);
            v3 += __shfl_xor_sync(FULLM, v3, off);
        }
        if (valid && quarter == 0) {
            if (which) { V2[k][0]=v0; V2[k][1]=v1; V2[k][2]=v2; V2[k][3]=v3; }
            else       { V1[k][0]=v0; V1[k][1]=v1; V1[k][2]=v2; V1[k][3]=v3; }
        }
    } else if (w == 9) {
        // Qn: (k9, half) = 18 items on one warp; lanes 18-31 padded (no write)
        const int idx = lane;
        int k9 = idx >> 1; if (k9 > 8) k9 = 8;
        const int half = idx & 1;
        const int cen = jlA(k9, A);
        const int h0 = half * 24;
        float q0=0,q1=0,q2=0,q3=0;
        #pragma unroll
        for (int hi = 0; hi < 24; hi++) {
            int hh = h0 + hi;
            float u = U1[9+k9][hh];
            float cf = f2a[cen][hh] * u * u;
            float4 wv = *(const float4*)&W2s[hh][0];
            q0 = fmaf(cf, wv.x, q0); q1 = fmaf(cf, wv.y, q1);
            q2 = fmaf(cf, wv.z, q2); q3 = fmaf(cf, wv.w, q3);
        }
        q0 += __shfl_xor_sync(FULLM, q0, 1);
        q1 += __shfl_xor_sync(FULLM, q1, 1);
        q2 += __shfl_xor_sync(FULLM, q2, 1);
        q3 += __shfl_xor_sync(FULLM, q3, 1);
        if (idx < 18 && half == 0) {
            Qn[k9][0]=q0; Qn[k9][1]=q1; Qn[k9][2]=q2; Qn[k9][3]=q3;
        }
    } else if (w >= 10 && w <= 12) {
        const int mu = w - 10;
        float q0=0,q1=0,q2=0,q3=0;
        #pragma unroll
        for (int rep = 0; rep < 2; rep++) {
            int hh = lane + rep*32;
            if (hh < HIDDEN) {
                float ud = 0.f;
                #pragma unroll
                for (int k = 0; k < 9; k++)
                    ud = fmaf(wdd[mu][k], U1[k][hh], ud);
                float cf = f2a[A][hh] * ud * ud;
                float4 wv = *(const float4*)&W2s[hh][0];
                q0 = fmaf(cf, wv.x, q0); q1 = fmaf(cf, wv.y, q1);
                q2 = fmaf(cf, wv.z, q2); q3 = fmaf(cf, wv.w, q3);
            }
        }
        #pragma unroll
        for (int off = 16; off > 0; off >>= 1) {
            q0 += __shfl_xor_sync(FULLM, q0, off);
            q1 += __shfl_xor_sync(FULLM, q1, off);
            q2 += __shfl_xor_sync(FULLM, q2, off);
            q3 += __shfl_xor_sync(FULLM, q3, off);
        }
        if (lane == 0) { QA[mu][0]=q0; QA[mu][1]=q1; QA[mu][2]=q2; QA[mu][3]=q3; }
    }
    __syncthreads();

    // -------- Phase D: mu-warps 0-2 only; per-warp REDG tail, no named barrier --------
    if (w >= 3) return;
    const int mu = w;
    float accA = 0.f;
    if (lane < 8) {
        int s = lane & 3;
        bool second = lane >= 4;
        #pragma unroll
        for (int k = 0; k < 9; k++) {
            float dd = wdd[mu][k], dh = wdh[mu][k];
            accA += second ? fmaf(dd*dd, V2[k][s], dh*V1[k][s])
                           : dd*V1[k][s];
        }
    }
    if (lane < 4)      wpd[mu][A][lane]   = accA;
    else if (lane < 8) wph[mu][A][lane-4] = accA + QA[mu][lane-4];
    __syncwarp();

    #pragma unroll
    for (int base = 0; base < 36; base += 32) {
        int item = base + lane;
        if (item < 36) {
            int k9 = item >> 2, s = item & 3;
            int kk = 9 + k9;
            float dd = wdd[mu][kk], dh = wdh[mu][kk];
            float pd = dd * V1[kk][s];
            float ph = dd*dd*(V2[kk][s] + Qn[k9][s]) + dh*V1[kk][s];
            int at = jlA(k9, A);
            wpd[mu][at][s] = pd;
            wph[mu][at][s] = ph;
        }
    }
    __syncwarp();

    float td = 0.f, th = 0.f;
    {
        int s = lane & 3, g = lane >> 2;
        for (int k = g; k < 9; k += 8) {
            int j = jlA(k, A);
            float ddc = wdd[mu][k], dhc = wdh[mu][k];
            float rdc = rad1k[k]*ddc;
            float rhc = fmaf(rad2k[k], ddc*ddc, rad1k[k]*dhc);
            td = fmaf(pv[j][s], rdc, td);
            th = fmaf(2.f*wpd[mu][j][s], rdc, fmaf(pv[j][s], rhc, th));
            float ddn = wdd[mu][9+k], dhn = wdh[mu][9+k];
            float rdn = rad1k[9+k]*ddn;
            float rhn = fmaf(rad2k[9+k], ddn*ddn, rad1k[9+k]*dhn);
            td = fmaf(pv[A][s], rdn, td);
            th = fmaf(2.f*wpd[mu][A][s], rdn, fmaf(pv[A][s], rhn, th));
        }
        for (int at = g; at < NATOMS; at += 8) {
            td = fmaf(wpd[mu][at][s], Rr[at], td);
            th = fmaf(wph[mu][at][s], Rr[at], th);
        }
        #pragma unroll
        for (int off = 4; off < 32; off <<= 1) {
            td += __shfl_xor_sync(FULLM, td, off);
            th += __shfl_xor_sync(FULLM, th, off);
        }
    }
    // lanes 0-3 hold (td, th) for s = lane. Compute Tval in-warp (no cross-warp dep).
    float Ts = 0.f;
    if (lane < NSTATES) {
        #pragma unroll
        for (int j = 0; j < NATOMS; j++)
            Ts = fmaf(pv[j][lane], Rr[j], Ts);
    }
    float T0 = __shfl_sync(FULLM, Ts, 0);
    if (lane < NSTATES) {
        float lap = (lane == 0) ? (2.f*td*td + 2.f*T0*th) : th;
        atomicAdd(&g_kinCS[c*NSTATES + lane], s_mass * lap);   // REDG
        if (mu == 0 && A == 0) g_T[c*NSTATES + lane] = Ts;
    }
    __threadfence();           // publish REDG + g_T before the counter
    __syncwarp();
    int flag = 0;
    if (lane == 0) {
        int old;
        asm volatile("atom.acq_rel.gpu.add.s32 %0, [%1], 1;"
                     : "=r"(old) : "l"(&g_fin) : "memory");
        flag = (old == NARRIVE - 1);
    }
    flag = __shfl_sync(FULLM, flag, 0);
    if (!flag) return;
    // last warp anywhere finalizes: lane = (config, state)
    const int s2 = lane & 3;
    float kin = -0.5f * g_kinCS[lane];
    float Tsg = g_T[lane];
    g_kinCS[lane] = 0.f;                     // reset for next graph replay
    float T0g = __shfl_sync(FULLM, Tsg, lane & ~3);
    float psi = (s2 == 0) ? T0g*T0g : Tsg;
    float pe  = potA - potLast;              // prefetched at Phase A (warps 0-2)
    float vib = (kin + psi*pe) / psi;
    float dvv = vib - s_el[s2];
    float l = dvv*dvv;
    #pragma unroll
    for (int off = 16; off > 0; off >>= 1)
        l += __shfl_xor_sync(FULLM, l, off);
    if (lane == 0) {
        out[0] = l;
        g_fin = 0;   // reset for next graph replay
    }
}

extern "C" void kernel_launch(void* const* d_in, const int* in_sizes, int n_in,
                              void* d_out, int out_size)
{
    // metadata order: eigen_weight, pot, cart, numatoms, species, massrev,
    //                 atom_index, shifts, W1, B1, W2, Emb, elevel
    const float* pot     = (const float*)d_in[1];
    const float* cart    = (const float*)d_in[2];
    const int*   species = (const int*)  d_in[4];
    const float* massrev = (const float*)d_in[5];
    const float* W1      = (const float*)d_in[8];
    const float* B1      = (const float*)d_in[9];
    const float* W2      = (const float*)d_in[10];
    const float* Emb     = (const float*)d_in[11];
    const float* elevel  = (const float*)d_in[12];

    fused_kernel<<<NBLOCKS, NT>>>(pot, cart, species, massrev,
                                  W1, B1, W2, Emb, elevel, (float*)d_out);
}

// round 16
// speedup vs baseline: 1.0238x; 1.0238x over previous
#include <cuda_runtime.h>

#define NCONF   8
#define NATOMS  10
#define NSTATES 4
#define NBASIS  24
#define HIDDEN  48
#define NTYPES  4
#define PPC     90            // ordered pairs, contiguous: p = i*9 + (j - (j>i))
#define NT      1024
#define NBLOCKS (NCONF*NATOMS)

#define PI_F 3.14159265358979323846f
#define CUT  6.0f
#define KARG (PI_F/CUT)
#define AL   1.5f
#define DLT  (CUT/23.0f)
#define FULLM 0xffffffffu

// cross-block scratch (no cudaMalloc allowed)
__device__ __align__(16) float g_kinCS[NCONF*NSTATES];
__device__ float g_T[NCONF*NSTATES];
__device__ int   g_fin;

__device__ __forceinline__ int jlA(int t, int A) { return t + (t >= A); }

__device__ __forceinline__ float fast_tanh(float u) {
    float ex = __expf(2.f*u);
    return 1.f - __fdividef(2.f, ex + 1.f);
}

__global__ void __launch_bounds__(NT, 1)
fused_kernel(const float* __restrict__ pot, const float* __restrict__ cart,
             const int* __restrict__ species, const float* __restrict__ massrev,
             const float* __restrict__ W1, const float* __restrict__ B1,
             const float* __restrict__ W2, const float* __restrict__ Emb,
             const float* __restrict__ elevel, float* __restrict__ out)
{
    __shared__ __align__(16) float W1s[NBASIS][52];
    __shared__ __align__(16) float W2s[HIDDEN][4];
    __shared__ float B1all[NTYPES][48];
    __shared__ float EmbAll[NTYPES][4];
    __shared__ int   s_sp[NATOMS];
    __shared__ float s_mass, s_el[4];
    __shared__ float G0[PPC][25];
    __shared__ float radv[PPC];
    __shared__ float G1k[18][25], G2k[18][25];
    __shared__ float rad1k[18], rad2k[18];
    __shared__ float wdd[3][18], wdh[3][18];
    __shared__ float Rr[NATOMS];
    __shared__ float tval[NATOMS][49], f1a[NATOMS][49], f2a[NATOMS][49];
    __shared__ __align__(16) float U1[18][52], U2[18][52];
    __shared__ float pv[NATOMS][4];
    __shared__ float V1[18][4], V2[18][4], Qn[9][4];
    __shared__ float QA[3][4];
    __shared__ float wpd[3][NATOMS][4], wph[3][NATOMS][4];
    __shared__ float Tval[4];
    __shared__ float Bsh[3][4], Hsh[3][4];

    const int tid  = threadIdx.x;
    const int w    = tid >> 5;
    const int lane = tid & 31;
    const int c    = blockIdx.x / NATOMS;
    const int A    = blockIdx.x % NATOMS;
    const float* cb = cart + c*NATOMS*3;

    // prefetch pot for the finalize path (warp 0 only)
    float potA = 0.f, potLast = 0.f;
    if (w == 0) { potA = pot[lane >> 2]; potLast = pot[NCONF-1]; }

    // -------- Phase A: weight loads + pair geometry, one phase --------
    if (tid < PPC) {
        const int p = tid;
        const int i = p / 9, jr = p % 9;
        const int j = jr + (jr >= i);
        float dx = cb[j*3+0] - cb[i*3+0];
        float dy = cb[j*3+1] - cb[i*3+1];
        float dz = cb[j*3+2] - cb[i*3+2];
        float d2 = fmaf(dx, dx, fmaf(dy, dy, dz*dz));
        float d  = sqrtf(d2);
        float arg = d * KARG;
        float sn = __sinf(arg), cs = __cosf(arg);
        radv[p] = sn*sn*sn;
        float f0 = (d < CUT) ? 0.5f*(cs + 1.f) : 0.f;

        const float gg = __expf(-2.f*AL*DLT*DLT);
        float gg2 = gg*gg, gg3 = gg2*gg, gg6 = gg3*gg3;
        float tc = __expf(fmaf(2.f*AL*DLT, d, -AL*DLT*DLT));
        float t0 = tc, t1 = tc*gg6, t2 = t1*gg6, t3 = t2*gg6;
        float rb0  = __expf(-AL*d2);
        float d6   = d -  6.f*DLT; float rb6  = __expf(-AL*d6*d6);
        float d12  = d - 12.f*DLT; float rb12 = __expf(-AL*d12*d12);
        float d18  = d - 18.f*DLT; float rb18 = __expf(-AL*d18*d18);
        #pragma unroll
        for (int i2 = 0; i2 < 6; i2++) {
            G0[p][i2]      = rb0 *f0;
            G0[p][6 + i2]  = rb6 *f0;
            G0[p][12 + i2] = rb12*f0;
            G0[p][18 + i2] = rb18*f0;
            rb0 *= t0; rb6 *= t1; rb12 *= t2; rb18 *= t3;
            t0 *= gg; t1 *= gg; t2 *= gg; t3 *= gg;
        }
    } else if (tid >= 96 && tid < 96 + 36) {
        // A-pair jets: (k, bhalf) split, 36 threads, direct cart loads
        const int idx = tid - 96;
        const int k     = idx >> 1;
        const int bhalf = idx & 1;
        const int b0    = bhalf * 12;
        const bool isC = (k < 9);
        const int i = isC ? A : jlA(k - 9, A);
        const int j = isC ? jlA(k, A) : A;
        float dx = cb[j*3+0] - cb[i*3+0];
        float dy = cb[j*3+1] - cb[i*3+1];
        float dz = cb[j*3+2] - cb[i*3+2];
        float d2 = fmaf(dx, dx, fmaf(dy, dy, dz*dz));
        float d  = sqrtf(d2);
        float arg = d * KARG;
        float sn = __sinf(arg), cs = __cosf(arg);
        float f0, fd1, fd2;
        if (d < CUT) {
            f0  = 0.5f*(cs + 1.f);
            fd1 = -0.5f*KARG*sn;
            fd2 = -0.5f*KARG*KARG*cs;
        } else { f0 = 0.f; fd1 = 0.f; fd2 = 0.f; }
        if (bhalf == 0) {
            rad1k[k] = 3.f*sn*sn*cs * KARG;
            rad2k[k] = (6.f*sn*cs*cs - 3.f*sn*sn*sn) * (KARG*KARG);
            float invd = __frcp_rn(d);
            float sgn = isC ? -1.f : 1.f;
            float ex = dx*invd, ey = dy*invd, ez = dz*invd;
            wdd[0][k] = sgn*ex; wdh[0][k] = (1.f - ex*ex)*invd;
            wdd[1][k] = sgn*ey; wdh[1][k] = (1.f - ey*ey)*invd;
            wdd[2][k] = sgn*ez; wdh[2][k] = (1.f - ez*ez)*invd;
        }
        const float gg = __expf(-2.f*AL*DLT*DLT);
        float gg2 = gg*gg, gg3 = gg2*gg, gg6 = gg3*gg3;
        float tc  = __expf(fmaf(2.f*AL*DLT, d, -AL*DLT*DLT));
        float ggb = bhalf ? gg6*gg6 : 1.f;
        float ta = tc * ggb;
        float tb = ta * gg6;
        float da  = d - (float)b0*DLT;      float rba = __expf(-AL*da*da);
        float db_ = d - (float)(b0+6)*DLT;  float rbb = __expf(-AL*db_*db_);
        #pragma unroll
        for (int i2 = 0; i2 < 6; i2++) {
            int ba = b0 + i2, bb = b0 + 6 + i2;
            float t_a = d - (float)ba*DLT;
            float r1a = -2.f*AL*t_a*rba;
            float r2a = (4.f*AL*AL*t_a*t_a - 2.f*AL)*rba;
            G1k[k][ba] = r1a*f0 + rba*fd1;
            G2k[k][ba] = r2a*f0 + 2.f*r1a*fd1 + rba*fd2;
            float t_b = d - (float)bb*DLT;
            float r1b = -2.f*AL*t_b*rbb;
            float r2b = (4.f*AL*AL*t_b*t_b - 2.f*AL)*rbb;
            G1k[k][bb] = r1b*f0 + rbb*fd1;
            G2k[k][bb] = r2b*f0 + 2.f*r1b*fd1 + rbb*fd2;
            rba *= ta; rbb *= tb; ta *= gg; tb *= gg;
        }
    } else if (tid >= 160 && tid < 160 + 384) {
        // W1 (1152 floats) on 384 threads (3 each)
        const int base = tid - 160;
        #pragma unroll
        for (int r = 0; r < 3; r++) {
            int i = base + r*384;
            W1s[i / HIDDEN][i % HIDDEN] = W1[i];
        }
    } else if (tid >= 544 && tid < 544 + 48) {
        const int base = tid - 544;
        #pragma unroll
        for (int r = 0; r < 4; r++) {
            int i = base + r*48;
            W2s[i >> 2][i & 3] = W2[i];
        }
    } else if (tid >= 592 && tid < 592 + 48) {
        const int base = tid - 592;
        #pragma unroll
        for (int r = 0; r < 4; r++) {
            int i = base + r*48;
            B1all[i / 48][i % 48] = B1[i];
        }
    } else if (tid >= 640 && tid < 640 + 16) {
        int i = tid - 640;
        EmbAll[i >> 2][i & 3] = Emb[i];
    } else if (tid >= 656 && tid < 656 + NATOMS) {
        s_sp[tid - 656] = species[c*NATOMS + (tid - 656)];
    } else if (tid == 666) {
        s_mass = massrev[c*NATOMS + A];
    } else if (tid >= 668 && tid < 668 + NSTATES) {
        s_el[tid - 668] = elevel[tid - 668];
    }
    __syncthreads();

    // -------- Phase B: U1/U2 + tanh (inline shfl-densv) + Rr, one phase --------
    if (tid < 448) {
        const int idx = tid;
        const bool valid = idx < 432;
        int k  = idx / 24; if (k > 17) k = 17;
        const int rem = idx % 24;
        const int hq = (rem >> 1) * 4;
        const int bhalf = rem & 1;
        const int b0 = bhalf * 12;
        float a0=0,a1=0,a2=0,a3=0, c0=0,c1=0,c2=0,c3=0;
        #pragma unroll
        for (int bi = 0; bi < 12; bi++) {
            int b = b0 + bi;
            float g1 = G1k[k][b], g2 = G2k[k][b];
            float4 wv = *(const float4*)&W1s[b][hq];
            a0 = fmaf(g1, wv.x, a0); a1 = fmaf(g1, wv.y, a1);
            a2 = fmaf(g1, wv.z, a2); a3 = fmaf(g1, wv.w, a3);
            c0 = fmaf(g2, wv.x, c0); c1 = fmaf(g2, wv.y, c1);
            c2 = fmaf(g2, wv.z, c2); c3 = fmaf(g2, wv.w, c3);
        }
        a0 += __shfl_xor_sync(FULLM, a0, 1);
        a1 += __shfl_xor_sync(FULLM, a1, 1);
        a2 += __shfl_xor_sync(FULLM, a2, 1);
        a3 += __shfl_xor_sync(FULLM, a3, 1);
        c0 += __shfl_xor_sync(FULLM, c0, 1);
        c1 += __shfl_xor_sync(FULLM, c1, 1);
        c2 += __shfl_xor_sync(FULLM, c2, 1);
        c3 += __shfl_xor_sync(FULLM, c3, 1);
        if (valid && bhalf == 0) {
            U1[k][hq]=a0; U1[k][hq+1]=a1; U1[k][hq+2]=a2; U1[k][hq+3]=a3;
            U2[k][hq]=c0; U2[k][hq+1]=c1; U2[k][hq+2]=c2; U2[k][hq+3]=c3;
        }
    } else if (w >= 14 && w < 14 + NATOMS) {
        // tanh path: warp = atom; lanes 0-23 own densv elements, shfl-broadcast
        const int at = w - 14;
        float dens = 0.f;
        if (lane < NBASIS) {
            float e0 = 0.f, e1 = 0.f;
            #pragma unroll
            for (int r = 0; r < 8; r += 2) {
                e0 += G0[at*9 + r][lane];
                e1 += G0[at*9 + r + 1][lane];
            }
            dens = e0 + e1 + G0[at*9 + 8][lane];
        }
        const int sp  = s_sp[at];
        const int hh1 = lane;               // 0..31
        const int hh2 = 32 + (lane & 15);   // lanes 0..15 write
        float uA0 = B1all[sp][hh1], uA1 = 0.f;
        float uB0 = B1all[sp][hh2], uB1 = 0.f;
        #pragma unroll
        for (int b = 0; b < NBASIS; b += 2) {
            float d0 = __shfl_sync(FULLM, dens, b);
            float d1 = __shfl_sync(FULLM, dens, b+1);
            uA0 = fmaf(d0, W1s[b  ][hh1], uA0);
            uA1 = fmaf(d1, W1s[b+1][hh1], uA1);
            uB0 = fmaf(d0, W1s[b  ][hh2], uB0);
            uB1 = fmaf(d1, W1s[b+1][hh2], uB1);
        }
        {
            float t1 = fast_tanh(uA0 + uA1);
            float f1 = 1.f - t1*t1;
            tval[at][hh1] = t1;
            f1a[at][hh1]  = f1;
            f2a[at][hh1]  = -2.f*t1*f1;
        }
        if (lane < 16) {
            float t2 = fast_tanh(uB0 + uB1);
            float f1 = 1.f - t2*t2;
            tval[at][hh2] = t2;
            f1a[at][hh2]  = f1;
            f2a[at][hh2]  = -2.f*t2*f1;
        }
    } else if (w == 24) {
        if (lane < NATOMS) {
            float r = 0.f;
            #pragma unroll
            for (int j = 0; j < NATOMS; j++)
                if (j != lane) r += radv[j*9 + (lane - (lane > j))];
            Rr[lane] = r;
        }
    }
    __syncthreads();

    // -------- Phase C: pv (w0-2), V1/V2 (w4-8), Qn (w9), QA (w10-12) --------
    if (w < 3) {
        const bool valid = tid < 80;
        int at = tid >> 3; if (at > 9) at = 9;
        const int s = (tid >> 1) & 3;
        const int half = tid & 1;
        const int h0 = half * 24;
        float a0 = 0.f, a1 = 0.f;
        #pragma unroll
        for (int hi = 0; hi < 24; hi += 2) {
            a0 = fmaf(tval[at][h0+hi  ], W2s[h0+hi  ][s], a0);
            a1 = fmaf(tval[at][h0+hi+1], W2s[h0+hi+1][s], a1);
        }
        float v = a0 + a1;
        v += __shfl_xor_sync(FULLM, v, 1);
        if (valid && half == 0) pv[at][s] = v + EmbAll[s_sp[at]][s];
    } else if (w >= 4 && w <= 8) {
        const int idx = tid - 128;
        const bool valid = idx < 144;
        int k = idx >> 3; if (k > 17) k = 17;
        const int which = (idx >> 2) & 1;
        const int quarter = idx & 3;
        const int cen = (k < 9) ? A : jlA(k - 9, A);
        const int h0 = quarter * 12;
        float v0=0,v1=0,v2=0,v3=0;
        #pragma unroll
        for (int hi = 0; hi < 12; hi++) {
            int hh = h0 + hi;
            float u = (which ? U2[k][hh] : U1[k][hh]) * f1a[cen][hh];
            float4 wv = *(const float4*)&W2s[hh][0];
            v0 = fmaf(u, wv.x, v0); v1 = fmaf(u, wv.y, v1);
            v2 = fmaf(u, wv.z, v2); v3 = fmaf(u, wv.w, v3);
        }
        #pragma unroll
        for (int off = 1; off <= 2; off <<= 1) {
            v0 += __shfl_xor_sync(FULLM, v0, off);
            v1 += __shfl_xor_sync(FULLM, v1, off);
            v2 += __shfl_xor_sync(FULLM, v2, off);
            v3 += __shfl_xor_sync(FULLM, v3, off);
        }
        if (valid && quarter == 0) {
            if (which) { V2[k][0]=v0; V2[k][1]=v1; V2[k][2]=v2; V2[k][3]=v3; }
            else       { V1[k][0]=v0; V1[k][1]=v1; V1[k][2]=v2; V1[k][3]=v3; }
        }
    } else if (w == 9) {
        // Qn: (k9, half) = 18 items on one warp; lanes 18-31 padded (no write)
        const int idx = lane;
        int k9 = idx >> 1; if (k9 > 8) k9 = 8;
        const int half = idx & 1;
        const int cen = jlA(k9, A);
        const int h0 = half * 24;
        float q0=0,q1=0,q2=0,q3=0;
        #pragma unroll
        for (int hi = 0; hi < 24; hi++) {
            int hh = h0 + hi;
            float u = U1[9+k9][hh];
            float cf = f2a[cen][hh] * u * u;
            float4 wv = *(const float4*)&W2s[hh][0];
            q0 = fmaf(cf, wv.x, q0); q1 = fmaf(cf, wv.y, q1);
            q2 = fmaf(cf, wv.z, q2); q3 = fmaf(cf, wv.w, q3);
        }
        q0 += __shfl_xor_sync(FULLM, q0, 1);
        q1 += __shfl_xor_sync(FULLM, q1, 1);
        q2 += __shfl_xor_sync(FULLM, q2, 1);
        q3 += __shfl_xor_sync(FULLM, q3, 1);
        if (idx < 18 && half == 0) {
            Qn[k9][0]=q0; Qn[k9][1]=q1; Qn[k9][2]=q2; Qn[k9][3]=q3;
        }
    } else if (w >= 10 && w <= 12) {
        const int mu = w - 10;
        float q0=0,q1=0,q2=0,q3=0;
        #pragma unroll
        for (int rep = 0; rep < 2; rep++) {
            int hh = lane + rep*32;
            if (hh < HIDDEN) {
                float ud = 0.f;
                #pragma unroll
                for (int k = 0; k < 9; k++)
                    ud = fmaf(wdd[mu][k], U1[k][hh], ud);
                float cf = f2a[A][hh] * ud * ud;
                float4 wv = *(const float4*)&W2s[hh][0];
                q0 = fmaf(cf, wv.x, q0); q1 = fmaf(cf, wv.y, q1);
                q2 = fmaf(cf, wv.z, q2); q3 = fmaf(cf, wv.w, q3);
            }
        }
        #pragma unroll
        for (int off = 16; off > 0; off >>= 1) {
            q0 += __shfl_xor_sync(FULLM, q0, off);
            q1 += __shfl_xor_sync(FULLM, q1, off);
            q2 += __shfl_xor_sync(FULLM, q2, off);
            q3 += __shfl_xor_sync(FULLM, q3, off);
        }
        if (lane == 0) { QA[mu][0]=q0; QA[mu][1]=q1; QA[mu][2]=q2; QA[mu][3]=q3; }
    }
    __syncthreads();

    // -------- Phase D: only warps 0-3 continue; the rest exit --------
    if (w >= 4) return;

    if (tid >= 96 && tid < 96 + NSTATES) {
        int s = tid - 96;
        float acc = 0.f;
        #pragma unroll
        for (int j = 0; j < NATOMS; j++)
            acc = fmaf(pv[j][s], Rr[j], acc);
        Tval[s] = acc;
    }
    if (w < 3) {
        const int mu = w;
        float accA = 0.f;
        if (lane < 8) {
            int s = lane & 3;
            bool second = lane >= 4;
            #pragma unroll
            for (int k = 0; k < 9; k++) {
                float dd = wdd[mu][k], dh = wdh[mu][k];
                accA += second ? fmaf(dd*dd, V2[k][s], dh*V1[k][s])
                               : dd*V1[k][s];
            }
        }
        if (lane < 4)      wpd[mu][A][lane]   = accA;
        else if (lane < 8) wph[mu][A][lane-4] = accA + QA[mu][lane-4];
        __syncwarp();

        #pragma unroll
        for (int base = 0; base < 36; base += 32) {
            int item = base + lane;
            if (item < 36) {
                int k9 = item >> 2, s = item & 3;
                int kk = 9 + k9;
                float dd = wdd[mu][kk], dh = wdh[mu][kk];
                float pd = dd * V1[kk][s];
                float ph = dd*dd*(V2[kk][s] + Qn[k9][s]) + dh*V1[kk][s];
                int at = jlA(k9, A);
                wpd[mu][at][s] = pd;
                wph[mu][at][s] = ph;
            }
        }
        __syncwarp();

        {
            int s = lane & 3, g = lane >> 2;
            float td = 0.f, th = 0.f;
            for (int k = g; k < 9; k += 8) {
                int j = jlA(k, A);
                float ddc = wdd[mu][k], dhc = wdh[mu][k];
                float rdc = rad1k[k]*ddc;
                float rhc = fmaf(rad2k[k], ddc*ddc, rad1k[k]*dhc);
                td = fmaf(pv[j][s], rdc, td);
                th = fmaf(2.f*wpd[mu][j][s], rdc, fmaf(pv[j][s], rhc, th));
                float ddn = wdd[mu][9+k], dhn = wdh[mu][9+k];
                float rdn = rad1k[9+k]*ddn;
                float rhn = fmaf(rad2k[9+k], ddn*ddn, rad1k[9+k]*dhn);
                td = fmaf(pv[A][s], rdn, td);
                th = fmaf(2.f*wpd[mu][A][s], rdn, fmaf(pv[A][s], rhn, th));
            }
            for (int at = g; at < NATOMS; at += 8) {
                td = fmaf(wpd[mu][at][s], Rr[at], td);
                th = fmaf(wph[mu][at][s], Rr[at], th);
            }
            #pragma unroll
            for (int off = 4; off < 32; off <<= 1) {
                td += __shfl_xor_sync(FULLM, td, off);
                th += __shfl_xor_sync(FULLM, th, off);
            }
            if (lane < 4) {
                Bsh[mu][lane] = td;
                Hsh[mu][lane] = th;
            }
        }
    }
    // named barrier over warps 0-3 only (128 threads)
    asm volatile("bar.sync 1, 128;" ::: "memory");

    // -------- Phase E: warp 0 only --------
    if (w != 0) return;
    if (tid < NSTATES) {
        int s = tid;
        float T0 = Tval[0];
        float acc = 0.f;
        #pragma unroll
        for (int mu = 0; mu < 3; mu++) {
            float Bv = Bsh[mu][s], Hv = Hsh[mu][s];
            acc += (s == 0) ? (2.f*Bv*Bv + 2.f*T0*Hv) : Hv;
        }
        atomicAdd(&g_kinCS[c*NSTATES + s], s_mass * acc);   // REDG, no return
        if (A == 0) g_T[c*NSTATES + s] = Tval[s];
    }
    __threadfence();           // publish REDG + g_T before the counter
    __syncwarp();
    int flag = 0;
    if (lane == 0) {
        int old;
        asm volatile("atom.acq_rel.gpu.add.s32 %0, [%1], 1;"
                     : "=r"(old) : "l"(&g_fin) : "memory");
        flag = (old == NBLOCKS - 1);
    }
    flag = __shfl_sync(FULLM, flag, 0);
    if (!flag) return;
    // last block: lane = (config, state); 32 contiguous accumulators
    const int s = tid & 3;
    float kin = -0.5f * g_kinCS[tid];
    float Ts = g_T[tid];
    g_kinCS[tid] = 0.f;                      // reset for next graph replay
    float T0 = __shfl_sync(FULLM, Ts, tid & ~3);
    float psi = (s == 0) ? T0*T0 : Ts;
    float pe  = potA - potLast;              // prefetched at Phase A
    float vib = (kin + psi*pe) / psi;
    float dvv = vib - s_el[s];
    float l = dvv*dvv;
    #pragma unroll
    for (int off = 16; off > 0; off >>= 1)
        l += __shfl_xor_sync(FULLM, l, off);
    if (tid == 0) {
        out[0] = l;
        g_fin = 0;   // reset for next graph replay
    }
}

extern "C" void kernel_launch(void* const* d_in, const int* in_sizes, int n_in,
                              void* d_out, int out_size)
{
    // metadata order: eigen_weight, pot, cart, numatoms, species, massrev,
    //                 atom_index, shifts, W1, B1, W2, Emb, elevel
    const float* pot     = (const float*)d_in[1];
    const float* cart    = (const float*)d_in[2];
    const int*   species = (const int*)  d_in[4];
    const float* massrev = (const float*)d_in[5];
    const float* W1      = (const float*)d_in[8];
    const float* B1      = (const float*)d_in[9];
    const float* W2      = (const float*)d_in[10];
    const float* Emb     = (const float*)d_in[11];
    const float* elevel  = (const float*)d_in[12];

    fused_kernel<<<NBLOCKS, NT>>>(pot, cart, species, massrev,
                                  W1, B1, W2, Emb, elevel, (float*)d_out);
}

// round 17
// speedup vs baseline: 1.0269x; 1.0030x over previous
#include <cuda_runtime.h>

#define NCONF   8
#define NATOMS  10
#define NSTATES 4
#define NBASIS  24
#define HIDDEN  48
#define NTYPES  4
#define PPC     90            // ordered pairs, contiguous: p = i*9 + (j - (j>i))
#define NT      1024
#define NBLOCKS (NCONF*NATOMS)

#define PI_F 3.14159265358979323846f
#define CUT  6.0f
#define KARG (PI_F/CUT)
#define AL   1.5f
#define DLT  (CUT/23.0f)
#define FULLM 0xffffffffu

// cross-block scratch (no cudaMalloc allowed)
__device__ __align__(16) float g_kinCS[NCONF*NSTATES];
__device__ float g_T[NCONF*NSTATES];
__device__ int   g_fin;

__device__ __forceinline__ int jlA(int t, int A) { return t + (t >= A); }

__device__ __forceinline__ float fast_tanh(float u) {
    float ex = __expf(2.f*u);
    return 1.f - __fdividef(2.f, ex + 1.f);
}

__global__ void __launch_bounds__(NT, 1)
fused_kernel(const float* __restrict__ pot, const float* __restrict__ cart,
             const int* __restrict__ species, const float* __restrict__ massrev,
             const float* __restrict__ W1, const float* __restrict__ B1,
             const float* __restrict__ W2, const float* __restrict__ Emb,
             const float* __restrict__ elevel, float* __restrict__ out)
{
    __shared__ __align__(16) float W1s[NBASIS][52];
    __shared__ __align__(16) float W2s[HIDDEN][4];
    __shared__ float B1all[NTYPES][48];
    __shared__ float EmbAll[NTYPES][4];
    __shared__ int   s_sp[NATOMS];
    __shared__ float s_mass, s_el[4];
    __shared__ float G0[PPC][25];
    __shared__ float radv[PPC];
    __shared__ float G1k[18][25], G2k[18][25];
    __shared__ float rad1k[18], rad2k[18];
    __shared__ float wdd[3][18], wdh[3][18];
    __shared__ float Rr[NATOMS];
    __shared__ float tval[NATOMS][49], f1a[NATOMS][49], f2a[NATOMS][49];
    __shared__ __align__(16) float U1[18][52], U2[18][52];
    __shared__ float pv[NATOMS][4];
    __shared__ float V1[18][4], V2[18][4], Qn[9][4];
    __shared__ float QA[3][4];
    __shared__ float wpd[3][NATOMS][4], wph[3][NATOMS][4];

    const int tid  = threadIdx.x;
    const int w    = tid >> 5;
    const int lane = tid & 31;
    const int c    = blockIdx.x / NATOMS;
    const int A    = blockIdx.x % NATOMS;
    const float* cb = cart + c*NATOMS*3;

    // prefetch pot for the finalize path (warp 0 only)
    float potA = 0.f, potLast = 0.f;
    if (w == 0) { potA = pot[lane >> 2]; potLast = pot[NCONF-1]; }

    // -------- Phase A: weight loads + pair geometry, one phase --------
    if (tid < PPC) {
        const int p = tid;
        const int i = p / 9, jr = p % 9;
        const int j = jr + (jr >= i);
        float dx = cb[j*3+0] - cb[i*3+0];
        float dy = cb[j*3+1] - cb[i*3+1];
        float dz = cb[j*3+2] - cb[i*3+2];
        float d2 = fmaf(dx, dx, fmaf(dy, dy, dz*dz));
        float d  = sqrtf(d2);
        float arg = d * KARG;
        float sn = __sinf(arg), cs = __cosf(arg);
        radv[p] = sn*sn*sn;
        float f0 = (d < CUT) ? 0.5f*(cs + 1.f) : 0.f;

        const float gg = __expf(-2.f*AL*DLT*DLT);
        float gg2 = gg*gg, gg3 = gg2*gg, gg6 = gg3*gg3;
        float tc = __expf(fmaf(2.f*AL*DLT, d, -AL*DLT*DLT));
        float t0 = tc, t1 = tc*gg6, t2 = t1*gg6, t3 = t2*gg6;
        float rb0  = __expf(-AL*d2);
        float d6   = d -  6.f*DLT; float rb6  = __expf(-AL*d6*d6);
        float d12  = d - 12.f*DLT; float rb12 = __expf(-AL*d12*d12);
        float d18  = d - 18.f*DLT; float rb18 = __expf(-AL*d18*d18);
        #pragma unroll
        for (int i2 = 0; i2 < 6; i2++) {
            G0[p][i2]      = rb0 *f0;
            G0[p][6 + i2]  = rb6 *f0;
            G0[p][12 + i2] = rb12*f0;
            G0[p][18 + i2] = rb18*f0;
            rb0 *= t0; rb6 *= t1; rb12 *= t2; rb18 *= t3;
            t0 *= gg; t1 *= gg; t2 *= gg; t3 *= gg;
        }
    } else if (tid >= 96 && tid < 96 + 36) {
        // A-pair jets: (k, bhalf) split, 36 threads, direct cart loads
        const int idx = tid - 96;
        const int k     = idx >> 1;
        const int bhalf = idx & 1;
        const int b0    = bhalf * 12;
        const bool isC = (k < 9);
        const int i = isC ? A : jlA(k - 9, A);
        const int j = isC ? jlA(k, A) : A;
        float dx = cb[j*3+0] - cb[i*3+0];
        float dy = cb[j*3+1] - cb[i*3+1];
        float dz = cb[j*3+2] - cb[i*3+2];
        float d2 = fmaf(dx, dx, fmaf(dy, dy, dz*dz));
        float d  = sqrtf(d2);
        float arg = d * KARG;
        float sn = __sinf(arg), cs = __cosf(arg);
        float f0, fd1, fd2;
        if (d < CUT) {
            f0  = 0.5f*(cs + 1.f);
            fd1 = -0.5f*KARG*sn;
            fd2 = -0.5f*KARG*KARG*cs;
        } else { f0 = 0.f; fd1 = 0.f; fd2 = 0.f; }
        if (bhalf == 0) {
            rad1k[k] = 3.f*sn*sn*cs * KARG;
            rad2k[k] = (6.f*sn*cs*cs - 3.f*sn*sn*sn) * (KARG*KARG);
            float invd = __frcp_rn(d);
            float sgn = isC ? -1.f : 1.f;
            float ex = dx*invd, ey = dy*invd, ez = dz*invd;
            wdd[0][k] = sgn*ex; wdh[0][k] = (1.f - ex*ex)*invd;
            wdd[1][k] = sgn*ey; wdh[1][k] = (1.f - ey*ey)*invd;
            wdd[2][k] = sgn*ez; wdh[2][k] = (1.f - ez*ez)*invd;
        }
        const float gg = __expf(-2.f*AL*DLT*DLT);
        float gg2 = gg*gg, gg3 = gg2*gg, gg6 = gg3*gg3;
        float tc  = __expf(fmaf(2.f*AL*DLT, d, -AL*DLT*DLT));
        float ggb = bhalf ? gg6*gg6 : 1.f;
        float ta = tc * ggb;
        float tb = ta * gg6;
        float da  = d - (float)b0*DLT;      float rba = __expf(-AL*da*da);
        float db_ = d - (float)(b0+6)*DLT;  float rbb = __expf(-AL*db_*db_);
        #pragma unroll
        for (int i2 = 0; i2 < 6; i2++) {
            int ba = b0 + i2, bb = b0 + 6 + i2;
            float t_a = d - (float)ba*DLT;
            float r1a = -2.f*AL*t_a*rba;
            float r2a = (4.f*AL*AL*t_a*t_a - 2.f*AL)*rba;
            G1k[k][ba] = r1a*f0 + rba*fd1;
            G2k[k][ba] = r2a*f0 + 2.f*r1a*fd1 + rba*fd2;
            float t_b = d - (float)bb*DLT;
            float r1b = -2.f*AL*t_b*rbb;
            float r2b = (4.f*AL*AL*t_b*t_b - 2.f*AL)*rbb;
            G1k[k][bb] = r1b*f0 + rbb*fd1;
            G2k[k][bb] = r2b*f0 + 2.f*r1b*fd1 + rbb*fd2;
            rba *= ta; rbb *= tb; ta *= gg; tb *= gg;
        }
    } else if (tid >= 160 && tid < 160 + 384) {
        // W1 (1152 floats) on 384 threads (3 each)
        const int base = tid - 160;
        #pragma unroll
        for (int r = 0; r < 3; r++) {
            int i = base + r*384;
            W1s[i / HIDDEN][i % HIDDEN] = W1[i];
        }
    } else if (tid >= 544 && tid < 544 + 48) {
        const int base = tid - 544;
        #pragma unroll
        for (int r = 0; r < 4; r++) {
            int i = base + r*48;
            W2s[i >> 2][i & 3] = W2[i];
        }
    } else if (tid >= 592 && tid < 592 + 48) {
        const int base = tid - 592;
        #pragma unroll
        for (int r = 0; r < 4; r++) {
            int i = base + r*48;
            B1all[i / 48][i % 48] = B1[i];
        }
    } else if (tid >= 640 && tid < 640 + 16) {
        int i = tid - 640;
        EmbAll[i >> 2][i & 3] = Emb[i];
    } else if (tid >= 656 && tid < 656 + NATOMS) {
        s_sp[tid - 656] = species[c*NATOMS + (tid - 656)];
    } else if (tid == 666) {
        s_mass = massrev[c*NATOMS + A];
    } else if (tid >= 668 && tid < 668 + NSTATES) {
        s_el[tid - 668] = elevel[tid - 668];
    }
    __syncthreads();

    // -------- Phase B: U1/U2 + tanh (inline shfl-densv) + Rr, one phase --------
    if (tid < 448) {
        const int idx = tid;
        const bool valid = idx < 432;
        int k  = idx / 24; if (k > 17) k = 17;
        const int rem = idx % 24;
        const int hq = (rem >> 1) * 4;
        const int bhalf = rem & 1;
        const int b0 = bhalf * 12;
        float a0=0,a1=0,a2=0,a3=0, c0=0,c1=0,c2=0,c3=0;
        #pragma unroll
        for (int bi = 0; bi < 12; bi++) {
            int b = b0 + bi;
            float g1 = G1k[k][b], g2 = G2k[k][b];
            float4 wv = *(const float4*)&W1s[b][hq];
            a0 = fmaf(g1, wv.x, a0); a1 = fmaf(g1, wv.y, a1);
            a2 = fmaf(g1, wv.z, a2); a3 = fmaf(g1, wv.w, a3);
            c0 = fmaf(g2, wv.x, c0); c1 = fmaf(g2, wv.y, c1);
            c2 = fmaf(g2, wv.z, c2); c3 = fmaf(g2, wv.w, c3);
        }
        a0 += __shfl_xor_sync(FULLM, a0, 1);
        a1 += __shfl_xor_sync(FULLM, a1, 1);
        a2 += __shfl_xor_sync(FULLM, a2, 1);
        a3 += __shfl_xor_sync(FULLM, a3, 1);
        c0 += __shfl_xor_sync(FULLM, c0, 1);
        c1 += __shfl_xor_sync(FULLM, c1, 1);
        c2 += __shfl_xor_sync(FULLM, c2, 1);
        c3 += __shfl_xor_sync(FULLM, c3, 1);
        if (valid && bhalf == 0) {
            U1[k][hq]=a0; U1[k][hq+1]=a1; U1[k][hq+2]=a2; U1[k][hq+3]=a3;
            U2[k][hq]=c0; U2[k][hq+1]=c1; U2[k][hq+2]=c2; U2[k][hq+3]=c3;
        }
    } else if (w >= 14 && w < 14 + NATOMS) {
        // tanh path: warp = atom; lanes 0-23 own densv elements, shfl-broadcast
        const int at = w - 14;
        float dens = 0.f;
        if (lane < NBASIS) {
            float e0 = 0.f, e1 = 0.f;
            #pragma unroll
            for (int r = 0; r < 8; r += 2) {
                e0 += G0[at*9 + r][lane];
                e1 += G0[at*9 + r + 1][lane];
            }
            dens = e0 + e1 + G0[at*9 + 8][lane];
        }
        const int sp  = s_sp[at];
        const int hh1 = lane;               // 0..31
        const int hh2 = 32 + (lane & 15);   // lanes 0..15 write
        float uA0 = B1all[sp][hh1], uA1 = 0.f;
        float uB0 = B1all[sp][hh2], uB1 = 0.f;
        #pragma unroll
        for (int b = 0; b < NBASIS; b += 2) {
            float d0 = __shfl_sync(FULLM, dens, b);
            float d1 = __shfl_sync(FULLM, dens, b+1);
            uA0 = fmaf(d0, W1s[b  ][hh1], uA0);
            uA1 = fmaf(d1, W1s[b+1][hh1], uA1);
            uB0 = fmaf(d0, W1s[b  ][hh2], uB0);
            uB1 = fmaf(d1, W1s[b+1][hh2], uB1);
        }
        {
            float t1 = fast_tanh(uA0 + uA1);
            float f1 = 1.f - t1*t1;
            tval[at][hh1] = t1;
            f1a[at][hh1]  = f1;
            f2a[at][hh1]  = -2.f*t1*f1;
        }
        if (lane < 16) {
            float t2 = fast_tanh(uB0 + uB1);
            float f1 = 1.f - t2*t2;
            tval[at][hh2] = t2;
            f1a[at][hh2]  = f1;
            f2a[at][hh2]  = -2.f*t2*f1;
        }
    } else if (w == 24) {
        if (lane < NATOMS) {
            float r = 0.f;
            #pragma unroll
            for (int j = 0; j < NATOMS; j++)
                if (j != lane) r += radv[j*9 + (lane - (lane > j))];
            Rr[lane] = r;
        }
    }
    __syncthreads();

    // -------- Phase C: pv (w0-2), V1/V2 (w4-8), Qn (w9), QA (w10-12) --------
    if (w < 3) {
        const bool valid = tid < 80;
        int at = tid >> 3; if (at > 9) at = 9;
        const int s = (tid >> 1) & 3;
        const int half = tid & 1;
        const int h0 = half * 24;
        float a0 = 0.f, a1 = 0.f;
        #pragma unroll
        for (int hi = 0; hi < 24; hi += 2) {
            a0 = fmaf(tval[at][h0+hi  ], W2s[h0+hi  ][s], a0);
            a1 = fmaf(tval[at][h0+hi+1], W2s[h0+hi+1][s], a1);
        }
        float v = a0 + a1;
        v += __shfl_xor_sync(FULLM, v, 1);
        if (valid && half == 0) pv[at][s] = v + EmbAll[s_sp[at]][s];
    } else if (w >= 4 && w <= 8) {
        const int idx = tid - 128;
        const bool valid = idx < 144;
        int k = idx >> 3; if (k > 17) k = 17;
        const int which = (idx >> 2) & 1;
        const int quarter = idx & 3;
        const int cen = (k < 9) ? A : jlA(k - 9, A);
        const int h0 = quarter * 12;
        float v0=0,v1=0,v2=0,v3=0;
        #pragma unroll
        for (int hi = 0; hi < 12; hi++) {
            int hh = h0 + hi;
            float u = (which ? U2[k][hh] : U1[k][hh]) * f1a[cen][hh];
            float4 wv = *(const float4*)&W2s[hh][0];
            v0 = fmaf(u, wv.x, v0); v1 = fmaf(u, wv.y, v1);
            v2 = fmaf(u, wv.z, v2); v3 = fmaf(u, wv.w, v3);
        }
        #pragma unroll
        for (int off = 1; off <= 2; off <<= 1) {
            v0 += __shfl_xor_sync(FULLM, v0, off);
            v1 += __shfl_xor_sync(FULLM, v1, off);
            v2 += __shfl_xor_sync(FULLM, v2, off);
            v3 += __shfl_xor_sync(FULLM, v3, off);
        }
        if (valid && quarter == 0) {
            if (which) { V2[k][0]=v0; V2[k][1]=v1; V2[k][2]=v2; V2[k][3]=v3; }
            else       { V1[k][0]=v0; V1[k][1]=v1; V1[k][2]=v2; V1[k][3]=v3; }
        }
    } else if (w == 9) {
        // Qn: (k9, half) = 18 items on one warp; lanes 18-31 padded (no write)
        const int idx = lane;
        int k9 = idx >> 1; if (k9 > 8) k9 = 8;
        const int half = idx & 1;
        const int cen = jlA(k9, A);
        const int h0 = half * 24;
        float q0=0,q1=0,q2=0,q3=0;
        #pragma unroll
        for (int hi = 0; hi < 24; hi++) {
            int hh = h0 + hi;
            float u = U1[9+k9][hh];
            float cf = f2a[cen][hh] * u * u;
            float4 wv = *(const float4*)&W2s[hh][0];
            q0 = fmaf(cf, wv.x, q0); q1 = fmaf(cf, wv.y, q1);
            q2 = fmaf(cf, wv.z, q2); q3 = fmaf(cf, wv.w, q3);
        }
        q0 += __shfl_xor_sync(FULLM, q0, 1);
        q1 += __shfl_xor_sync(FULLM, q1, 1);
        q2 += __shfl_xor_sync(FULLM, q2, 1);
        q3 += __shfl_xor_sync(FULLM, q3, 1);
        if (idx < 18 && half == 0) {
            Qn[k9][0]=q0; Qn[k9][1]=q1; Qn[k9][2]=q2; Qn[k9][3]=q3;
        }
    } else if (w >= 10 && w <= 12) {
        const int mu = w - 10;
        float q0=0,q1=0,q2=0,q3=0;
        #pragma unroll
        for (int rep = 0; rep < 2; rep++) {
            int hh = lane + rep*32;
            if (hh < HIDDEN) {
                float ud = 0.f;
                #pragma unroll
                for (int k = 0; k < 9; k++)
                    ud = fmaf(wdd[mu][k], U1[k][hh], ud);
                float cf = f2a[A][hh] * ud * ud;
                float4 wv = *(const float4*)&W2s[hh][0];
                q0 = fmaf(cf, wv.x, q0); q1 = fmaf(cf, wv.y, q1);
                q2 = fmaf(cf, wv.z, q2); q3 = fmaf(cf, wv.w, q3);
            }
        }
        #pragma unroll
        for (int off = 16; off > 0; off >>= 1) {
            q0 += __shfl_xor_sync(FULLM, q0, off);
            q1 += __shfl_xor_sync(FULLM, q1, off);
            q2 += __shfl_xor_sync(FULLM, q2, off);
            q3 += __shfl_xor_sync(FULLM, q3, off);
        }
        if (lane == 0) { QA[mu][0]=q0; QA[mu][1]=q1; QA[mu][2]=q2; QA[mu][3]=q3; }
    }
    __syncthreads();

    // -------- Phase D: mu-warps 0-2 only; per-mu REDG, single counter arrival --------
    if (w >= 3) return;
    const int mu = w;
    float accA = 0.f;
    if (lane < 8) {
        int s = lane & 3;
        bool second = lane >= 4;
        #pragma unroll
        for (int k = 0; k < 9; k++) {
            float dd = wdd[mu][k], dh = wdh[mu][k];
            accA += second ? fmaf(dd*dd, V2[k][s], dh*V1[k][s])
                           : dd*V1[k][s];
        }
    }
    if (lane < 4)      wpd[mu][A][lane]   = accA;
    else if (lane < 8) wph[mu][A][lane-4] = accA + QA[mu][lane-4];
    __syncwarp();

    #pragma unroll
    for (int base = 0; base < 36; base += 32) {
        int item = base + lane;
        if (item < 36) {
            int k9 = item >> 2, s = item & 3;
            int kk = 9 + k9;
            float dd = wdd[mu][kk], dh = wdh[mu][kk];
            float pd = dd * V1[kk][s];
            float ph = dd*dd*(V2[kk][s] + Qn[k9][s]) + dh*V1[kk][s];
            int at = jlA(k9, A);
            wpd[mu][at][s] = pd;
            wph[mu][at][s] = ph;
        }
    }
    __syncwarp();

    float td = 0.f, th = 0.f;
    {
        int s = lane & 3, g = lane >> 2;
        for (int k = g; k < 9; k += 8) {
            int j = jlA(k, A);
            float ddc = wdd[mu][k], dhc = wdh[mu][k];
            float rdc = rad1k[k]*ddc;
            float rhc = fmaf(rad2k[k], ddc*ddc, rad1k[k]*dhc);
            td = fmaf(pv[j][s], rdc, td);
            th = fmaf(2.f*wpd[mu][j][s], rdc, fmaf(pv[j][s], rhc, th));
            float ddn = wdd[mu][9+k], dhn = wdh[mu][9+k];
            float rdn = rad1k[9+k]*ddn;
            float rhn = fmaf(rad2k[9+k], ddn*ddn, rad1k[9+k]*dhn);
            td = fmaf(pv[A][s], rdn, td);
            th = fmaf(2.f*wpd[mu][A][s], rdn, fmaf(pv[A][s], rhn, th));
        }
        for (int at = g; at < NATOMS; at += 8) {
            td = fmaf(wpd[mu][at][s], Rr[at], td);
            th = fmaf(wph[mu][at][s], Rr[at], th);
        }
        #pragma unroll
        for (int off = 4; off < 32; off <<= 1) {
            td += __shfl_xor_sync(FULLM, td, off);
            th += __shfl_xor_sync(FULLM, th, off);
        }
    }
    // lanes 0-3 hold (td, th) for s = lane. Tval computed in-warp (bitwise
    // identical across the 3 mu-warps: same pv/Rr, same order).
    float Ts = 0.f;
    if (lane < NSTATES) {
        #pragma unroll
        for (int j = 0; j < NATOMS; j++)
            Ts = fmaf(pv[j][lane], Rr[j], Ts);
    }
    float T0 = __shfl_sync(FULLM, Ts, 0);
    if (lane < NSTATES) {
        float lap = (lane == 0) ? (2.f*td*td + 2.f*T0*th) : th;
        atomicAdd(&g_kinCS[c*NSTATES + lane], s_mass * lap);   // REDG, no return
        if (mu == 0 && A == 0) g_T[c*NSTATES + lane] = Ts;
    }
    __threadfence();           // each warp publishes its own REDG/g_T
    __syncwarp();
    if (mu != 0) {
        // non-blocking arrive; warps 1-2 exit immediately
        asm volatile("bar.arrive 1, 96;" ::: "memory");
        return;
    }
    // warp 0 waits for warps 1-2 arrivals (their fences precede their arrives)
    asm volatile("bar.sync 1, 96;" ::: "memory");
    int flag = 0;
    if (lane == 0) {
        int old;
        asm volatile("atom.acq_rel.gpu.add.s32 %0, [%1], 1;"
                     : "=r"(old) : "l"(&g_fin) : "memory");
        flag = (old == NBLOCKS - 1);
    }
    flag = __shfl_sync(FULLM, flag, 0);
    if (!flag) return;
    // last block: lane = (config, state); 32 contiguous accumulators
    const int s2 = lane & 3;
    float kin = -0.5f * g_kinCS[lane];
    float Tsg = g_T[lane];
    g_kinCS[lane] = 0.f;                     // reset for next graph replay
    float T0g = __shfl_sync(FULLM, Tsg, lane & ~3);
    float psi = (s2 == 0) ? T0g*T0g : Tsg;
    float pe  = potA - potLast;              // prefetched at Phase A
    float vib = (kin + psi*pe) / psi;
    float dvv = vib - s_el[s2];
    float l = dvv*dvv;
    #pragma unroll
    for (int off = 16; off > 0; off >>= 1)
        l += __shfl_xor_sync(FULLM, l, off);
    if (lane == 0) {
        out[0] = l;
        g_fin = 0;   // reset for next graph replay
    }
}

extern "C" void kernel_launch(void* const* d_in, const int* in_sizes, int n_in,
                              void* d_out, int out_size)
{
    // metadata order: eigen_weight, pot, cart, numatoms, species, massrev,
    //                 atom_index, shifts, W1, B1, W2, Emb, elevel
    const float* pot     = (const float*)d_in[1];
    const float* cart    = (const float*)d_in[2];
    const int*   species = (const int*)  d_in[4];
    const float* massrev = (const float*)d_in[5];
    const float* W1      = (const float*)d_in[8];
    const float* B1      = (const float*)d_in[9];
    const float* W2      = (const float*)d_in[10];
    const float* Emb     = (const float*)d_in[11];
    const float* elevel  = (const float*)d_in[12];

    fused_kernel<<<NBLOCKS, NT>>>(pot, cart, species, massrev,
                                  W1, B1, W2, Emb, elevel, (float*)d_out);
}